// round 5
// baseline (speedup 1.0000x reference)
#include <cuda_runtime.h>
#include <math.h>

// Problem constants (fixed by the benchmark)
#define NN   100000        // nodes
#define EE   1600000       // edges (without self loops)
#define GG   512           // graphs
#define DIMV 128           // hidden dim (== input feature dim)
#define LL   3             // GCN layers
#define BN_EPS 1e-5f

#define POOLSZ  (GG * 3 * DIMV)     // 196608
#define NODESZ  (NN * 3 * DIMV)     // 38400000

// ---------------------------------------------------------------------------
// Scratch (device globals -- no allocation allowed)
// ---------------------------------------------------------------------------
__device__ float g_h[NN * DIMV];        // layer input  (51.2 MB)
__device__ float g_hl[NN * DIMV];       // post-linear  (51.2 MB)
__device__ float g_acc[NN * DIMV];      // aggregation  (51.2 MB)
__device__ float g_norm[EE];            // edge norms
__device__ float g_dinv[NN];            // deg -> d^-1/2
__device__ float g_dinv2[NN];           // d^-1 (self loop norm)
__device__ float g_stats[2 * DIMV];     // per-column sum / sumsq
__device__ int   g_idx64;               // 1 if index tensors are int64
// Fallbacks in case d_out holds only one of the two reference outputs
__device__ float g_nodes_scratch[NODESZ];
__device__ float g_pool_scratch[POOLSZ];

// ---------------------------------------------------------------------------
// Index load helper: runtime int32 / int64 dispatch
// ---------------------------------------------------------------------------
__device__ __forceinline__ int ld_idx(const void* p, long long i) {
    if (g_idx64) return (int)__ldg(((const long long*)p) + i);
    return __ldg(((const int*)p) + i);
}

// Detect int64 vs int32: node indices < 2^17, so int64 little-endian words
// at odd positions are zero. For int32 those words are uniform in [0,1e5):
// P(4 accidental zeros) ~ 1e-20.
__global__ void detect_idx_kernel(const unsigned int* __restrict__ ei) {
    if (threadIdx.x == 0 && blockIdx.x == 0) {
        bool i64 = (ei[1] == 0u) && (ei[3] == 0u) && (ei[5] == 0u) && (ei[7] == 0u);
        g_idx64 = i64 ? 1 : 0;
    }
}

// ---------------------------------------------------------------------------
// Small utility kernels
// ---------------------------------------------------------------------------
__global__ void zero_kernel(float* __restrict__ p, int n) {
    int i = blockIdx.x * blockDim.x + threadIdx.x;
    if (i < n) p[i] = 0.f;
}

__global__ void init_deg_kernel() {
    int i = blockIdx.x * blockDim.x + threadIdx.x;
    if (i < NN) g_dinv[i] = 1.0f;          // self-loop weight
}

__global__ void scatter_deg_kernel(const void* __restrict__ ei,
                                   const float* __restrict__ ew) {
    int e = blockIdx.x * blockDim.x + threadIdx.x;
    if (e >= EE) return;
    int dst = ld_idx(ei, (long long)EE + e);   // col
    atomicAdd(&g_dinv[dst], __ldg(ew + e));
}

__global__ void finish_deg_kernel() {
    int i = blockIdx.x * blockDim.x + threadIdx.x;
    if (i >= NN) return;
    float d = g_dinv[i];
    float v = (d > 0.f) ? rsqrtf(d) : 0.f;
    g_dinv[i] = v;
    g_dinv2[i] = v * v;
}

__global__ void compute_norm_kernel(const void* __restrict__ ei,
                                    const float* __restrict__ ew) {
    int e = blockIdx.x * blockDim.x + threadIdx.x;
    if (e >= EE) return;
    int src = ld_idx(ei, e);
    int dst = ld_idx(ei, (long long)EE + e);
    g_norm[e] = g_dinv[src] * __ldg(ew + e) * g_dinv[dst];
}

__global__ void zero_stats_kernel() {
    if (threadIdx.x < 2 * DIMV) g_stats[threadIdx.x] = 0.f;
}

// acc = dinv2 * hl   (self-loop contribution; also zero-initializes acc)
__global__ void acc_init_kernel() {
    int i = blockIdx.x * blockDim.x + threadIdx.x;   // float4 index
    if (i >= NN * 32) return;
    int r = i >> 5;
    float d2 = g_dinv2[r];
    float4 v = ((const float4*)g_hl)[i];
    v.x *= d2; v.y *= d2; v.z *= d2; v.w *= d2;
    ((float4*)g_acc)[i] = v;
}

// ---------------------------------------------------------------------------
// GEMM: C[i][j] = sum_k A[i][k] * B[j][k]     (A: nrows x 128, B: 128 x 128)
// No smem: B (64 KB) lives in L1; A fragment loads broadcast inside the warp.
// 256 threads; per thread an 8x8 fragment. FFMA-bound.
// ---------------------------------------------------------------------------
__global__ __launch_bounds__(256) void gemm_rk128(const float* __restrict__ A,
                                                  const float* __restrict__ B,
                                                  float* __restrict__ C,
                                                  int nrows) {
    const int tx = threadIdx.x & 15;    // j-group: all 16 values inside a warp
    const int ty = threadIdx.x >> 4;    // i-group: 2 values per warp
    const int row0 = blockIdx.x * 128 + ty * 8;
    const int j0 = tx * 8;
    const float4* A4 = (const float4*)A;
    const float4* B4 = (const float4*)B;

    float acc[8][8];
#pragma unroll
    for (int m = 0; m < 8; m++)
#pragma unroll
        for (int n = 0; n < 8; n++) acc[m][n] = 0.f;

    int rm[8];
#pragma unroll
    for (int m = 0; m < 8; m++) {
        int r = row0 + m;
        rm[m] = (r < nrows) ? r : (nrows - 1);   // clamp for tail block
    }

#pragma unroll 1
    for (int kc = 0; kc < 32; kc++) {            // 4 k-values per step
        float4 bf[8];
#pragma unroll
        for (int n = 0; n < 8; n++) bf[n] = __ldg(&B4[(j0 + n) * 32 + kc]);
#pragma unroll
        for (int m = 0; m < 8; m++) {
            float4 a = __ldg(&A4[(size_t)rm[m] * 32 + kc]);
#pragma unroll
            for (int n = 0; n < 8; n++) {
                acc[m][n] = fmaf(a.x, bf[n].x, acc[m][n]);
                acc[m][n] = fmaf(a.y, bf[n].y, acc[m][n]);
                acc[m][n] = fmaf(a.z, bf[n].z, acc[m][n]);
                acc[m][n] = fmaf(a.w, bf[n].w, acc[m][n]);
            }
        }
    }

#pragma unroll
    for (int m = 0; m < 8; m++) {
        int r = row0 + m;
        if (r < nrows) {
            float4* Cr = (float4*)(C + (size_t)r * 128 + j0);
            Cr[0] = make_float4(acc[m][0], acc[m][1], acc[m][2], acc[m][3]);
            Cr[1] = make_float4(acc[m][4], acc[m][5], acc[m][6], acc[m][7]);
        }
    }
}

// ---------------------------------------------------------------------------
// Edge scatter: acc[col] += norm * hl[row].  One warp per edge, coalesced
// 128B loads and coalesced atomicAdd wavefronts.
// ---------------------------------------------------------------------------
__global__ __launch_bounds__(256) void edge_scatter_kernel(const void* __restrict__ ei) {
    int e = (blockIdx.x * blockDim.x + threadIdx.x) >> 5;
    if (e >= EE) return;
    int lane = threadIdx.x & 31;
    int src = ld_idx(ei, e);
    int dst = ld_idx(ei, (long long)EE + e);
    float w = __ldg(g_norm + e);
    const float* s = g_hl + (size_t)src * 128 + lane;
    float* d = g_acc + (size_t)dst * 128 + lane;
#pragma unroll
    for (int q = 0; q < 4; q++)
        atomicAdd(d + 32 * q, w * __ldg(s + 32 * q));
}

// ---------------------------------------------------------------------------
// y = relu(acc + bias); in-place; accumulate per-column sum / sumsq.
// Block covers 128 rows; thread (c, rl) walks rows rl, rl+2, ... (coalesced).
// ---------------------------------------------------------------------------
__global__ __launch_bounds__(256) void relu_stats_kernel(const float* __restrict__ bias) {
    int c  = threadIdx.x & 127;
    int rl = threadIdx.x >> 7;
    int r0 = blockIdx.x * 128;
    int rend = min(r0 + 128, NN);
    float bc = __ldg(bias + c);
    float s = 0.f, s2 = 0.f;
    for (int r = r0 + rl; r < rend; r += 2) {
        int idx = r * 128 + c;
        float v = g_acc[idx] + bc;
        v = v > 0.f ? v : 0.f;
        g_acc[idx] = v;
        s += v;
        s2 += v * v;
    }
    atomicAdd(&g_stats[c], s);
    atomicAdd(&g_stats[128 + c], s2);
}

// ---------------------------------------------------------------------------
// BatchNorm apply + write layer output (h for next layer, node feature slab)
// + graph pooling (sorted batch -> run-length local accumulation).
// ---------------------------------------------------------------------------
__global__ __launch_bounds__(256) void bn_pool_kernel(const float* __restrict__ gamma,
                                                      const float* __restrict__ beta,
                                                      const void* __restrict__ batch,
                                                      float* __restrict__ nodes,  // + l*128
                                                      float* __restrict__ pool) { // + l*128
    int c  = threadIdx.x & 127;
    int rl = threadIdx.x >> 7;
    int r0 = blockIdx.x * 128;
    int rend = min(r0 + 128, NN);

    const float invN = 1.0f / (float)NN;
    float mean = g_stats[c] * invN;
    float var  = g_stats[128 + c] * invN - mean * mean;
    float istd = rsqrtf(var + BN_EPS);
    float scl = istd * __ldg(gamma + c);
    float sft = __ldg(beta + c) - mean * scl;

    int curg = -1;
    float psum = 0.f;
    for (int r = r0 + rl; r < rend; r += 2) {
        int idx = r * 128 + c;
        float v = g_acc[idx] * scl + sft;
        g_h[idx] = v;                               // next layer input
        nodes[(size_t)r * 384 + c] = v;             // xs output slab
        int gid = ld_idx(batch, r);
        if (gid != curg) {
            if (curg >= 0) atomicAdd(pool + (size_t)curg * 384 + c, psum);
            psum = 0.f;
            curg = gid;
        }
        psum += v;
    }
    if (curg >= 0) atomicAdd(pool + (size_t)curg * 384 + c, psum);
}

// ---------------------------------------------------------------------------
// Launch
// ---------------------------------------------------------------------------
extern "C" void kernel_launch(void* const* d_in, const int* in_sizes, int n_in,
                              void* d_out, int out_size) {
    const float* x     = (const float*)d_in[0];
    const void*  ei    = d_in[1];                 // edge_index (int32 or int64)
    const float* ew    = (const float*)d_in[2];
    const void*  batch = d_in[3];
    const float* fc_w  = (const float*)d_in[4];
    const float* W     = (const float*)d_in[5];
    const float* b     = (const float*)d_in[6];
    const float* gamma = (const float*)d_in[7];
    const float* beta  = (const float*)d_in[8];

    float* out = (float*)d_out;
    float* pool;
    float* nodes;
    if (out_size >= POOLSZ + NODESZ) {            // tuple order: (pooled, xs)
        pool = out;
        nodes = out + POOLSZ;
    } else if (out_size == NODESZ) {              // only node features requested
        void* p; cudaGetSymbolAddress(&p, g_pool_scratch);
        pool = (float*)p;
        nodes = out;
    } else {                                      // only pooled requested
        void* p; cudaGetSymbolAddress(&p, g_nodes_scratch);
        pool = out;
        nodes = (float*)p;
    }

    const int T = 256;
    const int nbRow  = (NN + 127) / 128;                  // 782
    const int nbN    = (NN + T - 1) / T;
    const int nbE    = (EE + T - 1) / T;
    const int nbEdge = (EE * 32 + T - 1) / T;             // warp per edge
    const int nbVec  = (NN * 32 + T - 1) / T;             // float4 elementwise

    detect_idx_kernel<<<1, 32>>>((const unsigned int*)ei);
    zero_kernel<<<(POOLSZ + T - 1) / T, T>>>(pool, POOLSZ);

    // gcn_norm
    init_deg_kernel<<<nbN, T>>>();
    scatter_deg_kernel<<<nbE, T>>>(ei, ew);
    finish_deg_kernel<<<nbN, T>>>();
    compute_norm_kernel<<<nbE, T>>>(ei, ew);

    // fc: h = x @ fc_w^T
    {
        void* ph; cudaGetSymbolAddress(&ph, g_h);
        gemm_rk128<<<nbRow, T>>>(x, fc_w, (float*)ph, NN);
    }

    void* ph;  cudaGetSymbolAddress(&ph, g_h);
    void* phl; cudaGetSymbolAddress(&phl, g_hl);

    for (int l = 0; l < LL; l++) {
        gemm_rk128<<<nbRow, T>>>((const float*)ph, W + (size_t)l * DIMV * DIMV,
                                 (float*)phl, NN);
        acc_init_kernel<<<nbVec, T>>>();
        zero_stats_kernel<<<1, T>>>();
        edge_scatter_kernel<<<nbEdge, T>>>(ei);
        relu_stats_kernel<<<nbRow, T>>>(b + (size_t)l * DIMV);
        bn_pool_kernel<<<nbRow, T>>>(gamma + (size_t)l * DIMV,
                                     beta + (size_t)l * DIMV,
                                     batch,
                                     nodes + (size_t)l * DIMV,
                                     pool + (size_t)l * DIMV);
    }
}

// round 6
// speedup vs baseline: 1.2798x; 1.2798x over previous
#include <cuda_runtime.h>
#include <math.h>

// Problem constants (fixed by the benchmark)
#define NN   100000        // nodes
#define EE   1600000       // edges (without self loops)
#define GG   512           // graphs
#define DIMV 128           // hidden dim (== input feature dim)
#define LL   3             // GCN layers
#define BN_EPS 1e-5f

#define POOLSZ  (GG * 3 * DIMV)     // 196608
#define NODESZ  (NN * 3 * DIMV)     // 38400000

#define SCAN_B 1024
#define NBLK   ((NN + SCAN_B - 1) / SCAN_B)   // 98

// ---------------------------------------------------------------------------
// Scratch (device globals -- no allocation allowed)
// ---------------------------------------------------------------------------
__device__ float g_h[NN * DIMV];        // layer input  (51.2 MB)
__device__ float g_hl[NN * DIMV];       // post-linear  (51.2 MB)
__device__ float g_acc[NN * DIMV];      // aggregation  (51.2 MB)
__device__ float g_dinv[NN];            // deg -> d^-1/2
__device__ float g_dinv2[NN];           // d^-1 (self loop norm)
__device__ int   g_cnt[NN];             // in-degree counts / fill cursors
__device__ int   g_rowstart[NN + 1];    // CSR row offsets (by dst)
__device__ int2  g_csr[EE];             // (src, norm-as-bits) per edge, dst-grouped
__device__ int   g_bsum[NBLK];
__device__ int   g_boff[NBLK];
__device__ float g_stats[2 * DIMV];     // per-column sum / sumsq
__device__ int   g_idx64;               // 1 if index tensors are int64
// Fallbacks in case d_out holds only one of the two reference outputs
__device__ float g_nodes_scratch[NODESZ];
__device__ float g_pool_scratch[POOLSZ];

// ---------------------------------------------------------------------------
// f32x2 packed-FMA helpers (Blackwell: ptxas never auto-fuses FFMA2)
// ---------------------------------------------------------------------------
typedef unsigned long long u64;
__device__ __forceinline__ u64 pk2(float lo, float hi) {
    u64 r; asm("mov.b64 %0, {%1,%2};" : "=l"(r) : "f"(lo), "f"(hi)); return r;
}
__device__ __forceinline__ void fma2(u64& d, u64 a, u64 b) {
    asm("fma.rn.f32x2 %0, %1, %2, %0;" : "+l"(d) : "l"(a), "l"(b));
}
__device__ __forceinline__ float2 upk2(u64 v) {
    float2 f; asm("mov.b64 {%0,%1}, %2;" : "=f"(f.x), "=f"(f.y) : "l"(v)); return f;
}

// ---------------------------------------------------------------------------
// Index load helper: runtime int32 / int64 dispatch
// ---------------------------------------------------------------------------
__device__ __forceinline__ int ld_idx(const void* p, long long i) {
    if (g_idx64) return (int)__ldg(((const long long*)p) + i);
    return __ldg(((const int*)p) + i);
}

// Detect int64 vs int32: node indices < 2^17, so int64 little-endian words
// at odd positions are zero. For int32 those words are uniform in [0,1e5):
// P(4 accidental zeros) ~ 1e-20.
__global__ void detect_idx_kernel(const unsigned int* __restrict__ ei) {
    if (threadIdx.x == 0 && blockIdx.x == 0) {
        bool i64 = (ei[1] == 0u) && (ei[3] == 0u) && (ei[5] == 0u) && (ei[7] == 0u);
        g_idx64 = i64 ? 1 : 0;
    }
}

// ---------------------------------------------------------------------------
// Small utility kernels
// ---------------------------------------------------------------------------
__global__ void zero_kernel(float* __restrict__ p, int n) {
    int i = blockIdx.x * blockDim.x + threadIdx.x;
    if (i < n) p[i] = 0.f;
}

__global__ void init_deg_kernel() {
    int i = blockIdx.x * blockDim.x + threadIdx.x;
    if (i < NN) { g_dinv[i] = 1.0f; g_cnt[i] = 0; }   // self-loop weight
}

__global__ void count_deg_kernel(const void* __restrict__ ei,
                                 const float* __restrict__ ew) {
    int e = blockIdx.x * blockDim.x + threadIdx.x;
    if (e >= EE) return;
    int dst = ld_idx(ei, (long long)EE + e);   // col
    atomicAdd(&g_dinv[dst], __ldg(ew + e));
    atomicAdd(&g_cnt[dst], 1);
}

__global__ void finish_deg_kernel() {
    int i = blockIdx.x * blockDim.x + threadIdx.x;
    if (i >= NN) return;
    float d = g_dinv[i];
    float v = (d > 0.f) ? rsqrtf(d) : 0.f;
    g_dinv[i] = v;
    g_dinv2[i] = v * v;
}

__global__ void zero_stats_kernel() {
    if (threadIdx.x < 2 * DIMV) g_stats[threadIdx.x] = 0.f;
}

// ---------------------------------------------------------------------------
// 3-phase exclusive scan of g_cnt -> g_rowstart
// ---------------------------------------------------------------------------
__global__ void scan1_kernel() {
    __shared__ int sm[SCAN_B];
    int t = threadIdx.x;
    int g = blockIdx.x * SCAN_B + t;
    int v = (g < NN) ? g_cnt[g] : 0;
    sm[t] = v; __syncthreads();
    for (int off = 1; off < SCAN_B; off <<= 1) {
        int x = (t >= off) ? sm[t - off] : 0;
        __syncthreads();
        sm[t] += x;
        __syncthreads();
    }
    if (t == SCAN_B - 1) g_bsum[blockIdx.x] = sm[t];
}

__global__ void scan2_kernel() {
    if (threadIdx.x == 0 && blockIdx.x == 0) {
        int run = 0;
        for (int i = 0; i < NBLK; i++) { g_boff[i] = run; run += g_bsum[i]; }
        g_rowstart[NN] = run;   // == EE
    }
}

__global__ void scan3_kernel() {
    __shared__ int sm[SCAN_B];
    int t = threadIdx.x;
    int g = blockIdx.x * SCAN_B + t;
    int v = (g < NN) ? g_cnt[g] : 0;
    sm[t] = v; __syncthreads();
    for (int off = 1; off < SCAN_B; off <<= 1) {
        int x = (t >= off) ? sm[t - off] : 0;
        __syncthreads();
        sm[t] += x;
        __syncthreads();
    }
    if (g < NN) {
        g_rowstart[g] = g_boff[blockIdx.x] + sm[t] - v;   // exclusive
        g_cnt[g] = 0;                                     // reuse as fill cursor
    }
}

// Fill CSR grouped by dst; stores (src, norm) packed per edge.
__global__ void fill_csr_kernel(const void* __restrict__ ei,
                                const float* __restrict__ ew) {
    int e = blockIdx.x * blockDim.x + threadIdx.x;
    if (e >= EE) return;
    int src = ld_idx(ei, e);
    int dst = ld_idx(ei, (long long)EE + e);
    float nrm = g_dinv[src] * __ldg(ew + e) * g_dinv[dst];
    int pos = g_rowstart[dst] + atomicAdd(&g_cnt[dst], 1);
    g_csr[pos] = make_int2(src, __float_as_int(nrm));
}

// ---------------------------------------------------------------------------
// GEMM: C[i][j] = sum_k A[i][k] * B[j][k]     (A: nrows x 128, B: 128 x 128)
// No smem: B (64 KB) lives in L1; A fragment loads broadcast inside the warp.
// fma.rn.f32x2 packed FMA: lo accumulates even-k, hi odd-k products.
// ---------------------------------------------------------------------------
__global__ __launch_bounds__(256) void gemm_rk128(const float* __restrict__ A,
                                                  const float* __restrict__ B,
                                                  float* __restrict__ C,
                                                  int nrows) {
    const int tx = threadIdx.x & 15;    // j-group
    const int ty = threadIdx.x >> 4;    // i-group
    const int row0 = blockIdx.x * 128 + ty * 8;
    const int j0 = tx * 8;
    const float4* A4 = (const float4*)A;
    const float4* B4 = (const float4*)B;

    u64 acc[8][8];
#pragma unroll
    for (int m = 0; m < 8; m++)
#pragma unroll
        for (int n = 0; n < 8; n++) acc[m][n] = 0ull;

    int rm[8];
#pragma unroll
    for (int m = 0; m < 8; m++) {
        int r = row0 + m;
        rm[m] = (r < nrows) ? r : (nrows - 1);   // clamp for tail block
    }

#pragma unroll 1
    for (int kc = 0; kc < 32; kc++) {            // 4 k-values per step
        u64 b01[8], b23[8];
#pragma unroll
        for (int n = 0; n < 8; n++) {
            float4 bf = __ldg(&B4[(j0 + n) * 32 + kc]);
            b01[n] = pk2(bf.x, bf.y);
            b23[n] = pk2(bf.z, bf.w);
        }
#pragma unroll
        for (int m = 0; m < 8; m++) {
            float4 a = __ldg(&A4[(size_t)rm[m] * 32 + kc]);
            u64 a01 = pk2(a.x, a.y);
            u64 a23 = pk2(a.z, a.w);
#pragma unroll
            for (int n = 0; n < 8; n++) {
                fma2(acc[m][n], a01, b01[n]);
                fma2(acc[m][n], a23, b23[n]);
            }
        }
    }

#pragma unroll
    for (int m = 0; m < 8; m++) {
        int r = row0 + m;
        if (r < nrows) {
            float c[8];
#pragma unroll
            for (int n = 0; n < 8; n++) {
                float2 f = upk2(acc[m][n]);
                c[n] = f.x + f.y;
            }
            float4* Cr = (float4*)(C + (size_t)r * 128 + j0);
            Cr[0] = make_float4(c[0], c[1], c[2], c[3]);
            Cr[1] = make_float4(c[4], c[5], c[6], c[7]);
        }
    }
}

// ---------------------------------------------------------------------------
// CSR gather + self loop + bias + ReLU + BN statistics, fully fused.
// One warp per dst node (strided), lane owns 4 features (float4).
// No atomics in the edge loop; stats reduced via smem, 256 global atomics/blk.
// ---------------------------------------------------------------------------
__global__ __launch_bounds__(256) void gather_relu_stats_kernel(
        const float* __restrict__ bias) {
    __shared__ float st_s[DIMV], st_q[DIMV];
    const int lane = threadIdx.x & 31;
    const int warp = threadIdx.x >> 5;
    if (threadIdx.x < DIMV) { st_s[threadIdx.x] = 0.f; st_q[threadIdx.x] = 0.f; }
    __syncthreads();

    const int gw = blockIdx.x * 8 + warp;
    const int totw = gridDim.x * 8;
    const float4* hl4 = (const float4*)g_hl;
    float4* acc4 = (float4*)g_acc;
    const float4 b4 = ((const float4*)bias)[lane];

    float4 s = make_float4(0.f, 0.f, 0.f, 0.f);
    float4 q = make_float4(0.f, 0.f, 0.f, 0.f);

    for (int n = gw; n < NN; n += totw) {
        int st = g_rowstart[n];
        int en = g_rowstart[n + 1];
        float d2 = g_dinv2[n];
        float4 v = __ldg(&hl4[(size_t)n * 32 + lane]);
        float4 acc = make_float4(v.x * d2, v.y * d2, v.z * d2, v.w * d2);

        for (int i = st; i < en; i += 32) {
            int m = min(32, en - i);
            int srcl = 0; float wl = 0.f;
            if (lane < m) {
                int2 t = __ldg(&g_csr[i + lane]);
                srcl = t.x;
                wl = __int_as_float(t.y);
            }
            for (int j = 0; j < m; j++) {
                int src = __shfl_sync(0xffffffffu, srcl, j);
                float w = __shfl_sync(0xffffffffu, wl, j);
                float4 hv = __ldg(&hl4[(size_t)src * 32 + lane]);
                acc.x = fmaf(w, hv.x, acc.x);
                acc.y = fmaf(w, hv.y, acc.y);
                acc.z = fmaf(w, hv.z, acc.z);
                acc.w = fmaf(w, hv.w, acc.w);
            }
        }

        acc.x = fmaxf(acc.x + b4.x, 0.f);
        acc.y = fmaxf(acc.y + b4.y, 0.f);
        acc.z = fmaxf(acc.z + b4.z, 0.f);
        acc.w = fmaxf(acc.w + b4.w, 0.f);
        acc4[(size_t)n * 32 + lane] = acc;

        s.x += acc.x; q.x += acc.x * acc.x;
        s.y += acc.y; q.y += acc.y * acc.y;
        s.z += acc.z; q.z += acc.z * acc.z;
        s.w += acc.w; q.w += acc.w * acc.w;
    }

    int c0 = lane * 4;
    atomicAdd(&st_s[c0 + 0], s.x); atomicAdd(&st_q[c0 + 0], q.x);
    atomicAdd(&st_s[c0 + 1], s.y); atomicAdd(&st_q[c0 + 1], q.y);
    atomicAdd(&st_s[c0 + 2], s.z); atomicAdd(&st_q[c0 + 2], q.z);
    atomicAdd(&st_s[c0 + 3], s.w); atomicAdd(&st_q[c0 + 3], q.w);
    __syncthreads();
    if (threadIdx.x < DIMV) {
        atomicAdd(&g_stats[threadIdx.x], st_s[threadIdx.x]);
        atomicAdd(&g_stats[DIMV + threadIdx.x], st_q[threadIdx.x]);
    }
}

// ---------------------------------------------------------------------------
// BatchNorm apply + write layer output (h for next layer, node feature slab)
// + graph pooling (sorted batch -> run-length local accumulation).
// ---------------------------------------------------------------------------
__global__ __launch_bounds__(256) void bn_pool_kernel(const float* __restrict__ gamma,
                                                      const float* __restrict__ beta,
                                                      const void* __restrict__ batch,
                                                      float* __restrict__ nodes,  // + l*128
                                                      float* __restrict__ pool) { // + l*128
    int c  = threadIdx.x & 127;
    int rl = threadIdx.x >> 7;
    int r0 = blockIdx.x * 128;
    int rend = min(r0 + 128, NN);

    const float invN = 1.0f / (float)NN;
    float mean = g_stats[c] * invN;
    float var  = g_stats[128 + c] * invN - mean * mean;
    float istd = rsqrtf(var + BN_EPS);
    float scl = istd * __ldg(gamma + c);
    float sft = __ldg(beta + c) - mean * scl;

    int curg = -1;
    float psum = 0.f;
    for (int r = r0 + rl; r < rend; r += 2) {
        int idx = r * 128 + c;
        float v = g_acc[idx] * scl + sft;
        g_h[idx] = v;                               // next layer input
        nodes[(size_t)r * 384 + c] = v;             // xs output slab
        int gid = ld_idx(batch, r);
        if (gid != curg) {
            if (curg >= 0) atomicAdd(pool + (size_t)curg * 384 + c, psum);
            psum = 0.f;
            curg = gid;
        }
        psum += v;
    }
    if (curg >= 0) atomicAdd(pool + (size_t)curg * 384 + c, psum);
}

// ---------------------------------------------------------------------------
// Launch
// ---------------------------------------------------------------------------
extern "C" void kernel_launch(void* const* d_in, const int* in_sizes, int n_in,
                              void* d_out, int out_size) {
    const float* x     = (const float*)d_in[0];
    const void*  ei    = d_in[1];                 // edge_index (int32 or int64)
    const float* ew    = (const float*)d_in[2];
    const void*  batch = d_in[3];
    const float* fc_w  = (const float*)d_in[4];
    const float* W     = (const float*)d_in[5];
    const float* b     = (const float*)d_in[6];
    const float* gamma = (const float*)d_in[7];
    const float* beta  = (const float*)d_in[8];

    float* out = (float*)d_out;
    float* pool;
    float* nodes;
    if (out_size >= POOLSZ + NODESZ) {            // tuple order: (pooled, xs)
        pool = out;
        nodes = out + POOLSZ;
    } else if (out_size == NODESZ) {              // only node features requested
        void* p; cudaGetSymbolAddress(&p, g_pool_scratch);
        pool = (float*)p;
        nodes = out;
    } else {                                      // only pooled requested
        void* p; cudaGetSymbolAddress(&p, g_nodes_scratch);
        pool = out;
        nodes = (float*)p;
    }

    const int T = 256;
    const int nbRow  = (NN + 127) / 128;                  // 782
    const int nbN    = (NN + T - 1) / T;
    const int nbE    = (EE + T - 1) / T;

    detect_idx_kernel<<<1, 32>>>((const unsigned int*)ei);
    zero_kernel<<<(POOLSZ + T - 1) / T, T>>>(pool, POOLSZ);

    // gcn_norm + CSR build (amortized over all 3 layers)
    init_deg_kernel<<<nbN, T>>>();
    count_deg_kernel<<<nbE, T>>>(ei, ew);
    finish_deg_kernel<<<nbN, T>>>();
    scan1_kernel<<<NBLK, SCAN_B>>>();
    scan2_kernel<<<1, 32>>>();
    scan3_kernel<<<NBLK, SCAN_B>>>();
    fill_csr_kernel<<<nbE, T>>>(ei, ew);

    // fc: h = x @ fc_w^T
    void* ph;  cudaGetSymbolAddress(&ph, g_h);
    void* phl; cudaGetSymbolAddress(&phl, g_hl);
    gemm_rk128<<<nbRow, T>>>(x, fc_w, (float*)ph, NN);

    for (int l = 0; l < LL; l++) {
        gemm_rk128<<<nbRow, T>>>((const float*)ph, W + (size_t)l * DIMV * DIMV,
                                 (float*)phl, NN);
        zero_stats_kernel<<<1, T>>>();
        gather_relu_stats_kernel<<<592, T>>>(b + (size_t)l * DIMV);
        bn_pool_kernel<<<nbRow, T>>>(gamma + (size_t)l * DIMV,
                                     beta + (size_t)l * DIMV,
                                     batch,
                                     nodes + (size_t)l * DIMV,
                                     pool + (size_t)l * DIMV);
    }
}

// round 7
// speedup vs baseline: 1.7416x; 1.3609x over previous
#include <cuda_runtime.h>
#include <math.h>

// Problem constants (fixed by the benchmark)
#define NN   100000        // nodes
#define EE   1600000       // edges (without self loops)
#define GG   512           // graphs
#define DIMV 128           // hidden dim (== input feature dim)
#define LL   3             // GCN layers
#define BN_EPS 1e-5f

#define POOLSZ  (GG * 3 * DIMV)     // 196608
#define NODESZ  (NN * 3 * DIMV)     // 38400000

#define SCAN_B 1024
#define NBLK   ((NN + SCAN_B - 1) / SCAN_B)   // 98

// ---------------------------------------------------------------------------
// Scratch (device globals -- no allocation allowed)
// ---------------------------------------------------------------------------
__device__ float g_hl[NN * DIMV];       // post-linear  (51.2 MB)
__device__ float g_acc[NN * DIMV];      // aggregation  (51.2 MB)
__device__ float g_c0[DIMV * DIMV];     // fused W0 @ fc_w
__device__ float g_dinv[NN];            // deg -> d^-1/2
__device__ float g_dinv2[NN];           // d^-1 (self loop norm)
__device__ int   g_cnt[NN];             // in-degree counts / fill cursors
__device__ int   g_rowstart[NN + 1];    // CSR row offsets (by dst)
__device__ int2  g_csr[EE];             // (src, norm-as-bits) per edge, dst-grouped
__device__ int   g_bsum[NBLK];
__device__ int   g_boff[NBLK];
__device__ float g_stats[LL * 2 * DIMV];// per-layer column sum / sumsq
__device__ int   g_idx64;               // 1 if index tensors are int64
// Fallbacks in case d_out holds only one of the two reference outputs
__device__ float g_nodes_scratch[NODESZ];
__device__ float g_pool_scratch[POOLSZ];

// ---------------------------------------------------------------------------
// f32x2 packed-FMA helpers (Blackwell: ptxas never auto-fuses FFMA2)
// ---------------------------------------------------------------------------
typedef unsigned long long u64;
__device__ __forceinline__ u64 pk2(float lo, float hi) {
    u64 r; asm("mov.b64 %0, {%1,%2};" : "=l"(r) : "f"(lo), "f"(hi)); return r;
}
__device__ __forceinline__ void fma2(u64& d, u64 a, u64 b) {
    asm("fma.rn.f32x2 %0, %1, %2, %0;" : "+l"(d) : "l"(a), "l"(b));
}
__device__ __forceinline__ float2 upk2(u64 v) {
    float2 f; asm("mov.b64 {%0,%1}, %2;" : "=f"(f.x), "=f"(f.y) : "l"(v)); return f;
}

// ---------------------------------------------------------------------------
// Index load helper: runtime int32 / int64 dispatch
// ---------------------------------------------------------------------------
__device__ __forceinline__ int ld_idx(const void* p, long long i) {
    if (g_idx64) return (int)__ldg(((const long long*)p) + i);
    return __ldg(((const int*)p) + i);
}

// ---------------------------------------------------------------------------
// Fused prolog: int64 detect + zero pool + zero stats + init degree/counters
// ---------------------------------------------------------------------------
__global__ void prolog_kernel(const unsigned int* __restrict__ ei,
                              float* __restrict__ pool) {
    int i = blockIdx.x * blockDim.x + threadIdx.x;
    if (i == 0) {
        // node indices < 2^17: int64 high words are zero; int32 words are
        // uniform in [0,1e5): P(4 accidental zeros) ~ 1e-20.
        bool i64 = (ei[1] == 0u) && (ei[3] == 0u) && (ei[5] == 0u) && (ei[7] == 0u);
        g_idx64 = i64 ? 1 : 0;
    }
    if (i < LL * 2 * DIMV) g_stats[i] = 0.f;
    int tot = gridDim.x * blockDim.x;
    for (int j = i; j < POOLSZ; j += tot) pool[j] = 0.f;
    if (i < NN) { g_dinv[i] = 1.0f; g_cnt[i] = 0; }   // self-loop weight
}

__global__ void count_deg_kernel(const void* __restrict__ ei,
                                 const float* __restrict__ ew) {
    int e = blockIdx.x * blockDim.x + threadIdx.x;
    if (e >= EE) return;
    int dst = ld_idx(ei, (long long)EE + e);   // col
    atomicAdd(&g_dinv[dst], __ldg(ew + e));
    atomicAdd(&g_cnt[dst], 1);
}

__global__ void finish_deg_kernel() {
    int i = blockIdx.x * blockDim.x + threadIdx.x;
    if (i >= NN) return;
    float d = g_dinv[i];
    float v = (d > 0.f) ? rsqrtf(d) : 0.f;
    g_dinv[i] = v;
    g_dinv2[i] = v * v;
}

// ---------------------------------------------------------------------------
// 3-phase exclusive scan of g_cnt -> g_rowstart
// ---------------------------------------------------------------------------
__global__ void scan1_kernel() {
    __shared__ int sm[SCAN_B];
    int t = threadIdx.x;
    int g = blockIdx.x * SCAN_B + t;
    int v = (g < NN) ? g_cnt[g] : 0;
    sm[t] = v; __syncthreads();
    for (int off = 1; off < SCAN_B; off <<= 1) {
        int x = (t >= off) ? sm[t - off] : 0;
        __syncthreads();
        sm[t] += x;
        __syncthreads();
    }
    if (t == SCAN_B - 1) g_bsum[blockIdx.x] = sm[t];
}

__global__ void scan2_kernel() {
    if (threadIdx.x == 0 && blockIdx.x == 0) {
        int run = 0;
        for (int i = 0; i < NBLK; i++) { g_boff[i] = run; run += g_bsum[i]; }
        g_rowstart[NN] = run;   // == EE
    }
}

__global__ void scan3_kernel() {
    __shared__ int sm[SCAN_B];
    int t = threadIdx.x;
    int g = blockIdx.x * SCAN_B + t;
    int v = (g < NN) ? g_cnt[g] : 0;
    sm[t] = v; __syncthreads();
    for (int off = 1; off < SCAN_B; off <<= 1) {
        int x = (t >= off) ? sm[t - off] : 0;
        __syncthreads();
        sm[t] += x;
        __syncthreads();
    }
    if (g < NN) {
        g_rowstart[g] = g_boff[blockIdx.x] + sm[t] - v;   // exclusive
        g_cnt[g] = 0;                                     // reuse as fill cursor
    }
}

// Fill CSR grouped by dst; stores (src, norm) packed per edge.
__global__ void fill_csr_kernel(const void* __restrict__ ei,
                                const float* __restrict__ ew) {
    int e = blockIdx.x * blockDim.x + threadIdx.x;
    if (e >= EE) return;
    int src = ld_idx(ei, e);
    int dst = ld_idx(ei, (long long)EE + e);
    float nrm = g_dinv[src] * __ldg(ew + e) * g_dinv[dst];
    int pos = g_rowstart[dst] + atomicAdd(&g_cnt[dst], 1);
    g_csr[pos] = make_int2(src, __float_as_int(nrm));
}

// ---------------------------------------------------------------------------
// C0 = W0 @ fc_w : folds the fc layer into layer 0's weight (128x128x128).
// C0[j][f] = sum_d W0[j][d] * fcw[d][f]
// ---------------------------------------------------------------------------
__global__ void wfc_kernel(const float* __restrict__ W0,
                           const float* __restrict__ fcw) {
    int f = threadIdx.x;   // 128
    int j = blockIdx.x;    // 128
    float s = 0.f;
    for (int d = 0; d < DIMV; d++)
        s = fmaf(__ldg(W0 + j * DIMV + d), __ldg(fcw + d * DIMV + f), s);
    g_c0[j * DIMV + f] = s;
}

// ---------------------------------------------------------------------------
// GEMM: C[i][j] = sum_k A[i][k] * B[j][k]   (A: nrows x 128 @ row pitch lda4
// float4s, B: 128 x 128).  No smem: B (64 KB) lives in L1; A fragment loads
// broadcast inside the warp.  fma.rn.f32x2 packed FMA.
// ---------------------------------------------------------------------------
__global__ __launch_bounds__(256) void gemm_rk128(const float* __restrict__ A,
                                                  int lda4,
                                                  const float* __restrict__ B,
                                                  float* __restrict__ C,
                                                  int nrows) {
    const int tx = threadIdx.x & 15;    // j-group
    const int ty = threadIdx.x >> 4;    // i-group
    const int row0 = blockIdx.x * 128 + ty * 8;
    const int j0 = tx * 8;
    const float4* A4 = (const float4*)A;
    const float4* B4 = (const float4*)B;

    u64 acc[8][8];
#pragma unroll
    for (int m = 0; m < 8; m++)
#pragma unroll
        for (int n = 0; n < 8; n++) acc[m][n] = 0ull;

    int rm[8];
#pragma unroll
    for (int m = 0; m < 8; m++) {
        int r = row0 + m;
        rm[m] = (r < nrows) ? r : (nrows - 1);   // clamp for tail block
    }

#pragma unroll 1
    for (int kc = 0; kc < 32; kc++) {            // 4 k-values per step
        u64 b01[8], b23[8];
#pragma unroll
        for (int n = 0; n < 8; n++) {
            float4 bf = __ldg(&B4[(j0 + n) * 32 + kc]);
            b01[n] = pk2(bf.x, bf.y);
            b23[n] = pk2(bf.z, bf.w);
        }
#pragma unroll
        for (int m = 0; m < 8; m++) {
            float4 a = __ldg(&A4[(size_t)rm[m] * lda4 + kc]);
            u64 a01 = pk2(a.x, a.y);
            u64 a23 = pk2(a.z, a.w);
#pragma unroll
            for (int n = 0; n < 8; n++) {
                fma2(acc[m][n], a01, b01[n]);
                fma2(acc[m][n], a23, b23[n]);
            }
        }
    }

#pragma unroll
    for (int m = 0; m < 8; m++) {
        int r = row0 + m;
        if (r < nrows) {
            float c[8];
#pragma unroll
            for (int n = 0; n < 8; n++) {
                float2 f = upk2(acc[m][n]);
                c[n] = f.x + f.y;
            }
            float4* Cr = (float4*)(C + (size_t)r * 128 + j0);
            Cr[0] = make_float4(c[0], c[1], c[2], c[3]);
            Cr[1] = make_float4(c[4], c[5], c[6], c[7]);
        }
    }
}

// ---------------------------------------------------------------------------
// CSR gather + self loop + bias + ReLU + BN statistics, fully fused.
// One warp per dst node (strided), lane owns 4 features (float4).
// CSR entries broadcast-loaded by all lanes (one L1 line) -- no shuffles, so
// ptxas can software-pipeline the hv loads (unroll 4 -> MLP~4).
// ---------------------------------------------------------------------------
__global__ __launch_bounds__(256) void gather_relu_stats_kernel(
        const float* __restrict__ bias, float* __restrict__ stats) {
    __shared__ float st_s[DIMV], st_q[DIMV];
    const int lane = threadIdx.x & 31;
    const int warp = threadIdx.x >> 5;
    if (threadIdx.x < DIMV) { st_s[threadIdx.x] = 0.f; st_q[threadIdx.x] = 0.f; }
    __syncthreads();

    const int gw = blockIdx.x * 8 + warp;
    const int totw = gridDim.x * 8;
    const float4* hl4 = (const float4*)g_hl;
    float4* acc4 = (float4*)g_acc;
    const float4 b4 = ((const float4*)bias)[lane];

    float4 s = make_float4(0.f, 0.f, 0.f, 0.f);
    float4 q = make_float4(0.f, 0.f, 0.f, 0.f);

    for (int n = gw; n < NN; n += totw) {
        int st = __ldg(&g_rowstart[n]);
        int en = __ldg(&g_rowstart[n + 1]);
        float d2 = g_dinv2[n];
        float4 v = __ldg(&hl4[(size_t)n * 32 + lane]);
        float4 acc = make_float4(v.x * d2, v.y * d2, v.z * d2, v.w * d2);

#pragma unroll 4
        for (int i = st; i < en; i++) {
            int2 t = __ldg(&g_csr[i]);           // broadcast within warp
            float w = __int_as_float(t.y);
            float4 hv = __ldg(&hl4[(size_t)t.x * 32 + lane]);
            acc.x = fmaf(w, hv.x, acc.x);
            acc.y = fmaf(w, hv.y, acc.y);
            acc.z = fmaf(w, hv.z, acc.z);
            acc.w = fmaf(w, hv.w, acc.w);
        }

        acc.x = fmaxf(acc.x + b4.x, 0.f);
        acc.y = fmaxf(acc.y + b4.y, 0.f);
        acc.z = fmaxf(acc.z + b4.z, 0.f);
        acc.w = fmaxf(acc.w + b4.w, 0.f);
        acc4[(size_t)n * 32 + lane] = acc;

        s.x += acc.x; q.x += acc.x * acc.x;
        s.y += acc.y; q.y += acc.y * acc.y;
        s.z += acc.z; q.z += acc.z * acc.z;
        s.w += acc.w; q.w += acc.w * acc.w;
    }

    int c0 = lane * 4;
    atomicAdd(&st_s[c0 + 0], s.x); atomicAdd(&st_q[c0 + 0], q.x);
    atomicAdd(&st_s[c0 + 1], s.y); atomicAdd(&st_q[c0 + 1], q.y);
    atomicAdd(&st_s[c0 + 2], s.z); atomicAdd(&st_q[c0 + 2], q.z);
    atomicAdd(&st_s[c0 + 3], s.w); atomicAdd(&st_q[c0 + 3], q.w);
    __syncthreads();
    if (threadIdx.x < DIMV) {
        atomicAdd(&stats[threadIdx.x], st_s[threadIdx.x]);
        atomicAdd(&stats[DIMV + threadIdx.x], st_q[threadIdx.x]);
    }
}

// ---------------------------------------------------------------------------
// BatchNorm apply + write layer output slab + graph pooling (sorted batch ->
// run-length local accumulation).  float4 throughout.  The next layer's GEMM
// reads the nodes slab directly (stride 384), so no extra h buffer.
// ---------------------------------------------------------------------------
__global__ __launch_bounds__(256) void bn_pool_kernel(const float* __restrict__ gamma,
                                                      const float* __restrict__ beta,
                                                      const void* __restrict__ batch,
                                                      float* __restrict__ nodes,  // + l*128
                                                      float* __restrict__ pool,   // + l*128
                                                      const float* __restrict__ stats) {
    int c4 = threadIdx.x & 31;         // float4 column
    int rl = threadIdx.x >> 5;         // 8 row lanes
    int c0 = c4 * 4;
    int r0 = blockIdx.x * 128;
    int rend = min(r0 + 128, NN);

    const float invN = 1.0f / (float)NN;
    float4 sm = ((const float4*)stats)[c4];
    float4 sq = ((const float4*)(stats + DIMV))[c4];
    float4 gm = __ldg(&((const float4*)gamma)[c4]);
    float4 bt = __ldg(&((const float4*)beta)[c4]);
    float4 scl, sft;
    {
        float m, vv;
        m = sm.x * invN; vv = sq.x * invN - m * m; scl.x = rsqrtf(vv + BN_EPS) * gm.x; sft.x = bt.x - m * scl.x;
        m = sm.y * invN; vv = sq.y * invN - m * m; scl.y = rsqrtf(vv + BN_EPS) * gm.y; sft.y = bt.y - m * scl.y;
        m = sm.z * invN; vv = sq.z * invN - m * m; scl.z = rsqrtf(vv + BN_EPS) * gm.z; sft.z = bt.z - m * scl.z;
        m = sm.w * invN; vv = sq.w * invN - m * m; scl.w = rsqrtf(vv + BN_EPS) * gm.w; sft.w = bt.w - m * scl.w;
    }

    const float4* acc4 = (const float4*)g_acc;
    float4* nodes4 = (float4*)nodes;

    int curg = -1;
    float4 ps = make_float4(0.f, 0.f, 0.f, 0.f);
    for (int r = r0 + rl; r < rend; r += 8) {
        float4 a = acc4[(size_t)r * 32 + c4];
        float4 v;
        v.x = fmaf(a.x, scl.x, sft.x);
        v.y = fmaf(a.y, scl.y, sft.y);
        v.z = fmaf(a.z, scl.z, sft.z);
        v.w = fmaf(a.w, scl.w, sft.w);
        nodes4[(size_t)r * 96 + c4] = v;
        int gid = ld_idx(batch, r);
        if (gid != curg) {
            if (curg >= 0) {
                float* pp = pool + (size_t)curg * 384 + c0;
                atomicAdd(pp + 0, ps.x); atomicAdd(pp + 1, ps.y);
                atomicAdd(pp + 2, ps.z); atomicAdd(pp + 3, ps.w);
            }
            ps = make_float4(0.f, 0.f, 0.f, 0.f);
            curg = gid;
        }
        ps.x += v.x; ps.y += v.y; ps.z += v.z; ps.w += v.w;
    }
    if (curg >= 0) {
        float* pp = pool + (size_t)curg * 384 + c0;
        atomicAdd(pp + 0, ps.x); atomicAdd(pp + 1, ps.y);
        atomicAdd(pp + 2, ps.z); atomicAdd(pp + 3, ps.w);
    }
}

// ---------------------------------------------------------------------------
// Launch
// ---------------------------------------------------------------------------
extern "C" void kernel_launch(void* const* d_in, const int* in_sizes, int n_in,
                              void* d_out, int out_size) {
    const float* x     = (const float*)d_in[0];
    const void*  ei    = d_in[1];                 // edge_index (int32 or int64)
    const float* ew    = (const float*)d_in[2];
    const void*  batch = d_in[3];
    const float* fc_w  = (const float*)d_in[4];
    const float* W     = (const float*)d_in[5];
    const float* b     = (const float*)d_in[6];
    const float* gamma = (const float*)d_in[7];
    const float* beta  = (const float*)d_in[8];

    float* out = (float*)d_out;
    float* pool;
    float* nodes;
    if (out_size >= POOLSZ + NODESZ) {            // tuple order: (pooled, xs)
        pool = out;
        nodes = out + POOLSZ;
    } else if (out_size == NODESZ) {              // only node features requested
        void* p; cudaGetSymbolAddress(&p, g_pool_scratch);
        pool = (float*)p;
        nodes = out;
    } else {                                      // only pooled requested
        void* p; cudaGetSymbolAddress(&p, g_nodes_scratch);
        pool = out;
        nodes = (float*)p;
    }

    const int T = 256;
    const int nbRow = (NN + 127) / 128;                   // 782
    const int nbN   = (NN + T - 1) / T;
    const int nbE   = (EE + T - 1) / T;

    // fused prolog + gcn_norm + CSR build (amortized over all 3 layers)
    prolog_kernel<<<nbN, T>>>((const unsigned int*)ei, pool);
    count_deg_kernel<<<nbE, T>>>(ei, ew);
    finish_deg_kernel<<<nbN, T>>>();
    scan1_kernel<<<NBLK, SCAN_B>>>();
    scan2_kernel<<<1, 32>>>();
    scan3_kernel<<<NBLK, SCAN_B>>>();
    fill_csr_kernel<<<nbE, T>>>(ei, ew);

    // fold fc into layer 0: C0 = W0 @ fc_w
    wfc_kernel<<<DIMV, DIMV>>>(W, fc_w);

    void* pc0; cudaGetSymbolAddress(&pc0, g_c0);
    void* phl; cudaGetSymbolAddress(&phl, g_hl);

    for (int l = 0; l < LL; l++) {
        void* pstats; cudaGetSymbolAddress(&pstats, g_stats);
        float* stats = (float*)pstats + (size_t)l * 2 * DIMV;
        if (l == 0) {
            gemm_rk128<<<nbRow, T>>>(x, 32, (const float*)pc0, (float*)phl, NN);
        } else {
            gemm_rk128<<<nbRow, T>>>(nodes + (size_t)(l - 1) * DIMV, 96,
                                     W + (size_t)l * DIMV * DIMV, (float*)phl, NN);
        }
        gather_relu_stats_kernel<<<1184, T>>>(b + (size_t)l * DIMV, stats);
        bn_pool_kernel<<<nbRow, T>>>(gamma + (size_t)l * DIMV,
                                     beta + (size_t)l * DIMV,
                                     batch,
                                     nodes + (size_t)l * DIMV,
                                     pool + (size_t)l * DIMV,
                                     stats);
    }
}